// round 1
// baseline (speedup 1.0000x reference)
#include <cuda_runtime.h>

#define BB 64
#define NN 1024
#define FF 256
#define S_SLICES 8
#define PARTIALS (S_SLICES * 4)   // 32 partial h vectors per batch

// 64 * 32 * 256 floats = 2 MB scratch for GEMV partials (allocation-free rule)
__device__ float g_hpart[BB * PARTIALS * FF];

// ---------------------------------------------------------------------------
// adj output: identity copy for unmasked batches; for masked (num_nodes==N):
// out[i][j] = in[i+1][j+1] for i,j < N-1, zero on the last row/col.
// One block per (row, batch), 256 threads x float4 covers 1024 cols.
// ---------------------------------------------------------------------------
__global__ void adj_kernel(const float* __restrict__ adj,
                           const int* __restrict__ num_nodes,
                           float* __restrict__ adj_out) {
    const int b   = blockIdx.y;
    const int row = blockIdx.x;
    const int t   = threadIdx.x;           // 0..255, one float4 each
    const bool masked = num_nodes[b] >= NN;
    const size_t base = (size_t)b * NN * NN;

    float4* out4 = (float4*)(adj_out + base + (size_t)row * NN);
    if (!masked) {
        const float4* in4 = (const float4*)(adj + base + (size_t)row * NN);
        out4[t] = in4[t];
    } else {
        float4 v;
        if (row == NN - 1) {
            v = make_float4(0.f, 0.f, 0.f, 0.f);
        } else {
            const float* src = adj + base + (size_t)(row + 1) * NN;
            const int j = t * 4;
            v.x = src[j + 1];
            v.y = src[j + 2];
            v.z = src[j + 3];
            v.w = (j + 3 == NN - 1) ? 0.f : src[j + 4];
        }
        out4[t] = v;
    }
}

// ---------------------------------------------------------------------------
// nodes output + fused partial GEMV h = adj_row(nb) . nodes_new.
// Grid (S_SLICES, B), 256 threads. Thread t owns feature-quad f4 = t%64 and
// row residue msub = t/64 (rows advance by 4) -> fixed accumulator features.
// Writes its partial h quad to g_hpart[b][s*4+msub][f4*4..].
// ---------------------------------------------------------------------------
__global__ void nodes_kernel(const float* __restrict__ x,
                             const float* __restrict__ nodes,
                             const float* __restrict__ adj,
                             const int* __restrict__ num_nodes,
                             float* __restrict__ nodes_out) {
    const int b = blockIdx.y;
    const int s = blockIdx.x;
    const int t = threadIdx.x;
    const int nn = num_nodes[b];
    const bool masked = nn >= NN;
    const int nb = masked ? NN - 1 : nn;

    const int F4   = FF / 4;        // 64
    const int f4   = t % F4;
    const int msub = t / F4;        // 0..3
    const int rows_per_slice = NN / S_SLICES;   // 128
    const int row0 = s * rows_per_slice;

    const size_t nbase = (size_t)b * NN * FF;
    const float* adjrow = adj + (size_t)b * NN * NN + (size_t)nb * NN;
    const float4 xv = ((const float4*)(x + b * FF))[f4];

    float4 hacc = make_float4(0.f, 0.f, 0.f, 0.f);

    for (int m = row0 + msub; m < row0 + rows_per_slice; m += 4) {
        float4 v;
        if (m == nb) {
            v = xv;                               // scatter-write of new memory x
        } else {
            const int srcm = masked ? m + 1 : m;  // FIFO shift when wrapped
            v = ((const float4*)(nodes + nbase + (size_t)srcm * FF))[f4];
        }
        ((float4*)(nodes_out + nbase + (size_t)m * FF))[f4] = v;

        if (!masked) {                            // masked => adj row nb is all-zero
            const float a = __ldg(adjrow + m);
            hacc.x += a * v.x; hacc.y += a * v.y;
            hacc.z += a * v.z; hacc.w += a * v.w;
        }
    }

    const int p = s * 4 + msub;
    ((float4*)(g_hpart + ((size_t)b * PARTIALS + p) * FF))[f4] = hacc;
}

// ---------------------------------------------------------------------------
// mx = tanh(h @ W); also writes num_nodes+1 as float.
// Grid = B blocks, 256 threads (one output feature each).
// ---------------------------------------------------------------------------
__global__ void mx_kernel(const float* __restrict__ W,
                          const int* __restrict__ num_nodes,
                          float* __restrict__ mx,
                          float* __restrict__ nn_out) {
    const int b = blockIdx.x;
    const int t = threadIdx.x;
    __shared__ float h[FF];

    float acc = 0.f;
    const float* base = g_hpart + (size_t)b * PARTIALS * FF;
    #pragma unroll
    for (int p = 0; p < PARTIALS; p++) acc += base[p * FF + t];
    h[t] = acc;
    __syncthreads();

    float o = 0.f;
    #pragma unroll 8
    for (int f = 0; f < FF; f++) o += h[f] * W[f * FF + t];
    mx[b * FF + t] = tanhf(o);

    if (t == 0) {
        const int nn = num_nodes[b];
        nn_out[b] = (nn >= NN) ? (float)NN : (float)(nn + 1);
    }
}

// ---------------------------------------------------------------------------
// d_in: x[16384] f32, nodes[16777216] f32, adj[67108864] f32,
//       num_nodes[64] i32, W[65536] f32
// d_out (f32): mx[16384] | nodes[16777216] | adj[67108864] | num_nodes[64]
// ---------------------------------------------------------------------------
extern "C" void kernel_launch(void* const* d_in, const int* in_sizes, int n_in,
                              void* d_out, int out_size) {
    const float* x         = (const float*)d_in[0];
    const float* nodes     = (const float*)d_in[1];
    const float* adj       = (const float*)d_in[2];
    const int*   num_nodes = (const int*)  d_in[3];
    const float* W         = (const float*)d_in[4];

    float* out       = (float*)d_out;
    float* mx        = out;
    float* nodes_out = out + (size_t)BB * FF;
    float* adj_out   = nodes_out + (size_t)BB * NN * FF;
    float* nn_out    = adj_out + (size_t)BB * NN * NN;

    adj_kernel<<<dim3(NN, BB), 256>>>(adj, num_nodes, adj_out);
    nodes_kernel<<<dim3(S_SLICES, BB), 256>>>(x, nodes, adj, num_nodes, nodes_out);
    mx_kernel<<<BB, 256>>>(W, num_nodes, mx, nn_out);
}

// round 2
// speedup vs baseline: 1.0789x; 1.0789x over previous
#include <cuda_runtime.h>

#define BB 64
#define NN 1024
#define FF 256
#define S_SLICES 8
#define PARTIALS (S_SLICES * 4)      // 32 partial h vectors per batch
#define NODES_BLOCKS (S_SLICES * BB) // 512
#define ADJ_BLOCKS   (BB * NN)       // 65536

// 64 * 32 * 256 floats = 2 MB scratch for GEMV partials (allocation-free rule)
__device__ float g_hpart[BB * PARTIALS * FF];

// ---------------------------------------------------------------------------
// Fused kernel. Block order: [0, NODES_BLOCKS) = nodes copy + partial GEMV
// (long blocks, dispatched first so they overlap with the adj copy stream);
// [NODES_BLOCKS, NODES_BLOCKS+ADJ_BLOCKS) = adj copy (one row per block).
// ---------------------------------------------------------------------------
__global__ void __launch_bounds__(256) fused_kernel(
        const float* __restrict__ x,
        const float* __restrict__ nodes,
        const float* __restrict__ adj,
        const int* __restrict__ num_nodes,
        float* __restrict__ nodes_out,
        float* __restrict__ adj_out) {
    const int blk = blockIdx.x;
    const int t   = threadIdx.x;

    if (blk >= NODES_BLOCKS) {
        // ---------------- adj copy path ----------------
        const int k   = blk - NODES_BLOCKS;
        const int b   = k >> 10;           // / NN
        const int row = k & (NN - 1);      // % NN
        const bool masked = num_nodes[b] >= NN;
        const size_t base = (size_t)b * NN * NN;

        float4* out4 = (float4*)(adj_out + base + (size_t)row * NN);
        if (!masked) {
            const float4* in4 = (const float4*)(adj + base + (size_t)row * NN);
            out4[t] = in4[t];
        } else {
            float4 v;
            if (row == NN - 1) {
                v = make_float4(0.f, 0.f, 0.f, 0.f);
            } else {
                const float* src = adj + base + (size_t)(row + 1) * NN;
                const int j = t * 4;
                v.x = src[j + 1];
                v.y = src[j + 2];
                v.z = src[j + 3];
                v.w = (j + 3 == NN - 1) ? 0.f : src[j + 4];
            }
            out4[t] = v;
        }
        return;
    }

    // ---------------- nodes copy + partial GEMV path ----------------
    const int s = blk & (S_SLICES - 1);
    const int b = blk / S_SLICES;
    const int nn = num_nodes[b];
    const bool masked = nn >= NN;
    const int nb = masked ? NN - 1 : nn;

    const int F4   = FF / 4;                     // 64
    const int f4   = t & (F4 - 1);
    const int msub = t >> 6;                     // 0..3
    const int rows_per_slice = NN / S_SLICES;    // 128
    const int row0 = s * rows_per_slice;

    const size_t nbase = (size_t)b * NN * FF;
    const float* adjrow = adj + (size_t)b * NN * NN + (size_t)nb * NN;
    const float4 xv = ((const float4*)(x + b * FF))[f4];

    float4 hacc = make_float4(0.f, 0.f, 0.f, 0.f);

    #pragma unroll 4
    for (int m = row0 + msub; m < row0 + rows_per_slice; m += 4) {
        float4 v;
        if (m == nb) {
            v = xv;                               // scatter-write of new memory x
        } else {
            const int srcm = masked ? m + 1 : m;  // FIFO shift when wrapped
            v = ((const float4*)(nodes + nbase + (size_t)srcm * FF))[f4];
        }
        ((float4*)(nodes_out + nbase + (size_t)m * FF))[f4] = v;

        if (!masked) {                            // masked => adj row nb is all-zero
            const float a = __ldg(adjrow + m);
            hacc.x += a * v.x; hacc.y += a * v.y;
            hacc.z += a * v.z; hacc.w += a * v.w;
        }
    }

    const int p = s * 4 + msub;
    ((float4*)(g_hpart + ((size_t)b * PARTIALS + p) * FF))[f4] = hacc;
}

// ---------------------------------------------------------------------------
// mx = tanh(h @ W); also writes num_nodes+1 as float.
// Grid = B blocks, 256 threads (one output feature each).
// ---------------------------------------------------------------------------
__global__ void __launch_bounds__(256) mx_kernel(
        const float* __restrict__ W,
        const int* __restrict__ num_nodes,
        float* __restrict__ mx,
        float* __restrict__ nn_out) {
    const int b = blockIdx.x;
    const int t = threadIdx.x;
    __shared__ float h[FF];

    float acc = 0.f;
    const float* base = g_hpart + (size_t)b * PARTIALS * FF;
    #pragma unroll
    for (int p = 0; p < PARTIALS; p++) acc += base[p * FF + t];
    h[t] = acc;
    __syncthreads();

    float o = 0.f;
    #pragma unroll 8
    for (int f = 0; f < FF; f++) o += h[f] * W[f * FF + t];
    mx[b * FF + t] = tanhf(o);

    if (t == 0) {
        const int nn = num_nodes[b];
        nn_out[b] = (nn >= NN) ? (float)NN : (float)(nn + 1);
    }
}

// ---------------------------------------------------------------------------
// d_in: x[16384] f32, nodes[16777216] f32, adj[67108864] f32,
//       num_nodes[64] i32, W[65536] f32
// d_out (f32): mx[16384] | nodes[16777216] | adj[67108864] | num_nodes[64]
// ---------------------------------------------------------------------------
extern "C" void kernel_launch(void* const* d_in, const int* in_sizes, int n_in,
                              void* d_out, int out_size) {
    const float* x         = (const float*)d_in[0];
    const float* nodes     = (const float*)d_in[1];
    const float* adj       = (const float*)d_in[2];
    const int*   num_nodes = (const int*)  d_in[3];
    const float* W         = (const float*)d_in[4];

    float* out       = (float*)d_out;
    float* mx        = out;
    float* nodes_out = out + (size_t)BB * FF;
    float* adj_out   = nodes_out + (size_t)BB * NN * FF;
    float* nn_out    = adj_out + (size_t)BB * NN * NN;

    fused_kernel<<<NODES_BLOCKS + ADJ_BLOCKS, 256>>>(
        x, nodes, adj, num_nodes, nodes_out, adj_out);
    mx_kernel<<<BB, 256>>>(W, num_nodes, mx, nn_out);
}

// round 3
// speedup vs baseline: 1.1063x; 1.0254x over previous
#include <cuda_runtime.h>

#define BB 64
#define NN 1024
#define FF 256
#define S_SLICES 8
#define PARTIALS (S_SLICES * 4)      // 32 partial h vectors per batch
#define NODES_BLOCKS (S_SLICES * BB) // 512
#define ADJ_BLOCKS   (BB * NN)       // 65536
#define MX_BLOCKS    (BB * 4)        // 256 (batch x output-quarter)

// 2 MB scratch for GEMV partials + completion counter (allocation-free rule)
__device__ float g_hpart[BB * PARTIALS * FF];
__device__ unsigned int g_done;

// ---------------------------------------------------------------------------
// Fused kernel, three block classes by grid position:
//   [0, NODES_BLOCKS)                : nodes copy + partial GEMV (wave 1)
//   [NODES_BLOCKS, +ADJ_BLOCKS)      : adj copy (bulk DRAM stream)
//   last MX_BLOCKS                   : h-reduce + tanh(h@W) (scheduled last,
//                                      spin on g_done — already complete)
// ---------------------------------------------------------------------------
__global__ void __launch_bounds__(256) fused_kernel(
        const float* __restrict__ x,
        const float* __restrict__ nodes,
        const float* __restrict__ adj,
        const int* __restrict__ num_nodes,
        const float* __restrict__ W,
        float* __restrict__ nodes_out,
        float* __restrict__ adj_out,
        float* __restrict__ mx,
        float* __restrict__ nn_out) {
    const int blk = blockIdx.x;
    const int t   = threadIdx.x;

    if (blk >= NODES_BLOCKS + ADJ_BLOCKS) {
        // ---------------- mx path (last blocks) ----------------
        const int k = blk - (NODES_BLOCKS + ADJ_BLOCKS);
        const int b = k >> 2;            // batch
        const int q = k & 3;             // output quarter

        // wait for all nodes-blocks' partials (normally already done)
        if (t == 0) {
            while (atomicAdd(&g_done, 0u) < NODES_BLOCKS) { __nanosleep(64); }
        }
        __syncthreads();
        __threadfence();

        __shared__ float h[FF];
        __shared__ float red[4][64];

        // reduce 32 partials -> h[256]
        {
            const float* base = g_hpart + (size_t)b * PARTIALS * FF + t;
            float acc = 0.f;
            #pragma unroll
            for (int p = 0; p < PARTIALS; p++) acc += base[p * FF];
            h[t] = acc;
        }
        __syncthreads();

        // each thread: output o = q*64 + (t&63), f-slice p = t>>6 (64 f's)
        const int o  = (t & 63);
        const int fp = (t >> 6);
        const int f0 = fp * 64;
        const int oc = q * 64 + o;       // global output column
        float acc = 0.f;
        #pragma unroll 8
        for (int i = 0; i < 64; i++) {
            acc += h[f0 + i] * W[(size_t)(f0 + i) * FF + oc];
        }
        red[fp][o] = acc;
        __syncthreads();
        if (t < 64) {
            float s = red[0][t] + red[1][t] + red[2][t] + red[3][t];
            mx[(size_t)b * FF + q * 64 + t] = tanhf(s);
        }
        if (t == 0 && q == 0) {
            const int nn = num_nodes[b];
            nn_out[b] = (nn >= NN) ? (float)NN : (float)(nn + 1);
        }
        return;
    }

    if (blk >= NODES_BLOCKS) {
        // ---------------- adj copy path ----------------
        const int k   = blk - NODES_BLOCKS;
        const int b   = k >> 10;           // / NN
        const int row = k & (NN - 1);      // % NN
        const bool masked = num_nodes[b] >= NN;
        const size_t base = (size_t)b * NN * NN;

        float4* out4 = (float4*)(adj_out + base + (size_t)row * NN);
        if (!masked) {
            const float4* in4 = (const float4*)(adj + base + (size_t)row * NN);
            out4[t] = in4[t];
        } else {
            float4 v;
            if (row == NN - 1) {
                v = make_float4(0.f, 0.f, 0.f, 0.f);
            } else {
                const float* src = adj + base + (size_t)(row + 1) * NN;
                const int j = t * 4;
                v.x = src[j + 1];
                v.y = src[j + 2];
                v.z = src[j + 3];
                v.w = (j + 3 == NN - 1) ? 0.f : src[j + 4];
            }
            out4[t] = v;
        }
        return;
    }

    // ---------------- nodes copy + partial GEMV path ----------------
    const int s = blk & (S_SLICES - 1);
    const int b = blk / S_SLICES;
    const int nn = num_nodes[b];
    const bool masked = nn >= NN;
    const int nb = masked ? NN - 1 : nn;

    const int F4   = FF / 4;                     // 64
    const int f4   = t & (F4 - 1);
    const int msub = t >> 6;                     // 0..3
    const int rows_per_slice = NN / S_SLICES;    // 128
    const int row0 = s * rows_per_slice;

    const size_t nbase = (size_t)b * NN * FF;
    const float* adjrow = adj + (size_t)b * NN * NN + (size_t)nb * NN;
    const float4 xv = ((const float4*)(x + b * FF))[f4];

    float4 hacc = make_float4(0.f, 0.f, 0.f, 0.f);

    #pragma unroll 4
    for (int m = row0 + msub; m < row0 + rows_per_slice; m += 4) {
        float4 v;
        if (m == nb) {
            v = xv;                               // scatter-write of new memory x
        } else {
            const int srcm = masked ? m + 1 : m;  // FIFO shift when wrapped
            v = ((const float4*)(nodes + nbase + (size_t)srcm * FF))[f4];
        }
        ((float4*)(nodes_out + nbase + (size_t)m * FF))[f4] = v;

        if (!masked) {                            // masked => adj row nb is all-zero
            const float a = __ldg(adjrow + m);
            hacc.x += a * v.x; hacc.y += a * v.y;
            hacc.z += a * v.z; hacc.w += a * v.w;
        }
    }

    const int p = s * 4 + msub;
    ((float4*)(g_hpart + ((size_t)b * PARTIALS + p) * FF))[f4] = hacc;

    // publish this block's partials
    __syncthreads();
    __threadfence();
    if (t == 0) atomicAdd(&g_done, 1u);
}

// ---------------------------------------------------------------------------
// d_in: x[16384] f32, nodes[16777216] f32, adj[67108864] f32,
//       num_nodes[64] i32, W[65536] f32
// d_out (f32): mx[16384] | nodes[16777216] | adj[67108864] | num_nodes[64]
// ---------------------------------------------------------------------------
extern "C" void kernel_launch(void* const* d_in, const int* in_sizes, int n_in,
                              void* d_out, int out_size) {
    const float* x         = (const float*)d_in[0];
    const float* nodes     = (const float*)d_in[1];
    const float* adj       = (const float*)d_in[2];
    const int*   num_nodes = (const int*)  d_in[3];
    const float* W         = (const float*)d_in[4];

    float* out       = (float*)d_out;
    float* mx        = out;
    float* nodes_out = out + (size_t)BB * FF;
    float* adj_out   = nodes_out + (size_t)BB * NN * FF;
    float* nn_out    = adj_out + (size_t)BB * NN * NN;

    void* done_ptr = nullptr;
    cudaGetSymbolAddress(&done_ptr, g_done);
    cudaMemsetAsync(done_ptr, 0, sizeof(unsigned int));

    fused_kernel<<<NODES_BLOCKS + ADJ_BLOCKS + MX_BLOCKS, 256>>>(
        x, nodes, adj, num_nodes, W, nodes_out, adj_out, mx, nn_out);
}

// round 4
// speedup vs baseline: 1.1616x; 1.0500x over previous
#include <cuda_runtime.h>

#define BB 64
#define NN 1024
#define FF 256
#define S_SLICES 8
#define PARTIALS (S_SLICES * 4)      // 32 partial h vectors per batch
#define NODES_BLOCKS (S_SLICES * BB) // 512
#define ROWS_PER_ADJ_BLOCK 4
#define ADJ_BLOCKS   (BB * NN / ROWS_PER_ADJ_BLOCK)  // 16384
#define MX_BLOCKS    (BB * 4)        // 256 (batch x output-quarter)

// 2 MB scratch for GEMV partials + completion counter (allocation-free rule)
__device__ float g_hpart[BB * PARTIALS * FF];
__device__ unsigned int g_done;

// ---------------------------------------------------------------------------
// Fused kernel, three block classes by grid position:
//   [0, NODES_BLOCKS)           : nodes copy + partial GEMV (wave 1)
//   [NODES_BLOCKS, +ADJ_BLOCKS) : adj copy, 4 rows/block, MLP=4
//   last MX_BLOCKS              : h-reduce + tanh(h@W) (scheduled last)
// __launch_bounds__(256, 8): cap regs at 32 so 8 blocks/SM stay resident.
// ---------------------------------------------------------------------------
__global__ void __launch_bounds__(256, 8) fused_kernel(
        const float* __restrict__ x,
        const float* __restrict__ nodes,
        const float* __restrict__ adj,
        const int* __restrict__ num_nodes,
        const float* __restrict__ W,
        float* __restrict__ nodes_out,
        float* __restrict__ adj_out,
        float* __restrict__ mx,
        float* __restrict__ nn_out) {
    const int blk = blockIdx.x;
    const int t   = threadIdx.x;

    if (blk >= NODES_BLOCKS + ADJ_BLOCKS) {
        // ---------------- mx path (last blocks) ----------------
        const int k = blk - (NODES_BLOCKS + ADJ_BLOCKS);
        const int b = k >> 2;            // batch
        const int q = k & 3;             // output quarter

        if (t == 0) {
            while (atomicAdd(&g_done, 0u) < NODES_BLOCKS) { __nanosleep(64); }
        }
        __syncthreads();
        __threadfence();

        __shared__ float h[FF];
        __shared__ float red[4][64];

        // reduce 32 partials -> h[256]
        {
            const float* base = g_hpart + (size_t)b * PARTIALS * FF + t;
            float acc = 0.f;
            #pragma unroll
            for (int p = 0; p < PARTIALS; p++) acc += base[p * FF];
            h[t] = acc;
        }
        __syncthreads();

        const int o  = (t & 63);
        const int fp = (t >> 6);
        const int f0 = fp * 64;
        const int oc = q * 64 + o;       // global output column
        float acc = 0.f;
        #pragma unroll 8
        for (int i = 0; i < 64; i++) {
            acc += h[f0 + i] * W[(size_t)(f0 + i) * FF + oc];
        }
        red[fp][o] = acc;
        __syncthreads();
        if (t < 64) {
            float s = red[0][t] + red[1][t] + red[2][t] + red[3][t];
            mx[(size_t)b * FF + q * 64 + t] = tanhf(s);
        }
        if (t == 0 && q == 0) {
            const int nn = num_nodes[b];
            nn_out[b] = (nn >= NN) ? (float)NN : (float)(nn + 1);
        }
        return;
    }

    if (blk >= NODES_BLOCKS) {
        // ---------------- adj copy path: 4 rows, MLP=4 ----------------
        const int k  = blk - NODES_BLOCKS;
        const int rb = NN / ROWS_PER_ADJ_BLOCK;    // 256 blocks per batch
        const int b  = k / rb;
        const int r0 = (k % rb) * ROWS_PER_ADJ_BLOCK;
        const bool masked = num_nodes[b] >= NN;
        const size_t base = (size_t)b * NN * NN;

        if (!masked) {
            const float4* in4  = (const float4*)(adj + base);
            float4*       out4 = (float4*)(adj_out + base);
            const size_t i0 = (size_t)r0 * (NN / 4) + t;   // row = 256 float4
            // front-batched independent loads
            float4 v0 = in4[i0];
            float4 v1 = in4[i0 + 256];
            float4 v2 = in4[i0 + 512];
            float4 v3 = in4[i0 + 768];
            out4[i0]       = v0;
            out4[i0 + 256] = v1;
            out4[i0 + 512] = v2;
            out4[i0 + 768] = v3;
        } else {
            #pragma unroll
            for (int r = 0; r < ROWS_PER_ADJ_BLOCK; r++) {
                const int row = r0 + r;
                float4 v;
                if (row == NN - 1) {
                    v = make_float4(0.f, 0.f, 0.f, 0.f);
                } else {
                    const float* src = adj + base + (size_t)(row + 1) * NN;
                    const int j = t * 4;
                    v.x = src[j + 1];
                    v.y = src[j + 2];
                    v.z = src[j + 3];
                    v.w = (j + 3 == NN - 1) ? 0.f : src[j + 4];
                }
                ((float4*)(adj_out + base + (size_t)row * NN))[t] = v;
            }
        }
        return;
    }

    // ---------------- nodes copy + partial GEMV path ----------------
    const int s = blk & (S_SLICES - 1);
    const int b = blk / S_SLICES;
    const int nn = num_nodes[b];
    const bool masked = nn >= NN;
    const int nb = masked ? NN - 1 : nn;

    const int F4   = FF / 4;                     // 64
    const int f4   = t & (F4 - 1);
    const int msub = t >> 6;                     // 0..3
    const int rows_per_slice = NN / S_SLICES;    // 128
    const int row0 = s * rows_per_slice;

    const size_t nbase = (size_t)b * NN * FF;
    const float* adjrow = adj + (size_t)b * NN * NN + (size_t)nb * NN;
    const float4 xv = ((const float4*)(x + b * FF))[f4];

    float4 hacc = make_float4(0.f, 0.f, 0.f, 0.f);

    #pragma unroll 4
    for (int m = row0 + msub; m < row0 + rows_per_slice; m += 4) {
        float4 v;
        if (m == nb) {
            v = xv;                               // scatter-write of new memory x
        } else {
            const int srcm = masked ? m + 1 : m;  // FIFO shift when wrapped
            v = ((const float4*)(nodes + nbase + (size_t)srcm * FF))[f4];
        }
        ((float4*)(nodes_out + nbase + (size_t)m * FF))[f4] = v;

        if (!masked) {                            // masked => adj row nb is all-zero
            const float a = __ldg(adjrow + m);
            hacc.x += a * v.x; hacc.y += a * v.y;
            hacc.z += a * v.z; hacc.w += a * v.w;
        }
    }

    const int p = s * 4 + msub;
    ((float4*)(g_hpart + ((size_t)b * PARTIALS + p) * FF))[f4] = hacc;

    // publish this block's partials
    __syncthreads();
    __threadfence();
    if (t == 0) atomicAdd(&g_done, 1u);
}

// ---------------------------------------------------------------------------
// d_in: x[16384] f32, nodes[16777216] f32, adj[67108864] f32,
//       num_nodes[64] i32, W[65536] f32
// d_out (f32): mx[16384] | nodes[16777216] | adj[67108864] | num_nodes[64]
// ---------------------------------------------------------------------------
extern "C" void kernel_launch(void* const* d_in, const int* in_sizes, int n_in,
                              void* d_out, int out_size) {
    const float* x         = (const float*)d_in[0];
    const float* nodes     = (const float*)d_in[1];
    const float* adj       = (const float*)d_in[2];
    const int*   num_nodes = (const int*)  d_in[3];
    const float* W         = (const float*)d_in[4];

    float* out       = (float*)d_out;
    float* mx        = out;
    float* nodes_out = out + (size_t)BB * FF;
    float* adj_out   = nodes_out + (size_t)BB * NN * FF;
    float* nn_out    = adj_out + (size_t)BB * NN * NN;

    void* done_ptr = nullptr;
    cudaGetSymbolAddress(&done_ptr, g_done);
    cudaMemsetAsync(done_ptr, 0, sizeof(unsigned int));

    fused_kernel<<<NODES_BLOCKS + ADJ_BLOCKS + MX_BLOCKS, 256>>>(
        x, nodes, adj, num_nodes, W, nodes_out, adj_out, mx, nn_out);
}

// round 5
// speedup vs baseline: 1.1973x; 1.0307x over previous
#include <cuda_runtime.h>

#define BB 64
#define NN 1024
#define FF 256
#define S_SLICES 8
#define PARTIALS (S_SLICES * 4)      // 32 partial h vectors per batch
#define NODES_BLOCKS (S_SLICES * BB) // 512
#define ROWS_PER_ADJ_BLOCK 4
#define ADJ_BLOCKS   (BB * NN / ROWS_PER_ADJ_BLOCK)  // 16384
#define MX_BLOCKS    (BB * 4)        // 256 (batch x output-quarter)

// 2 MB scratch for GEMV partials + completion counters (allocation-free rule).
// Counters are self-resetting: zero-initialized at load, and the last mx
// block restores them to zero each launch, so no memset node is needed and
// the kernel stays deterministic across graph replays.
__device__ float g_hpart[BB * PARTIALS * FF];
__device__ unsigned int g_done;    // incremented by nodes blocks
__device__ unsigned int g_mxdone;  // incremented by mx blocks after their spin

// ---------------------------------------------------------------------------
// Fused kernel, three block classes by grid position:
//   [0, NODES_BLOCKS)           : nodes copy + partial GEMV (wave 1)
//   [NODES_BLOCKS, +ADJ_BLOCKS) : adj copy, 4 rows/block, MLP=4, streaming
//   last MX_BLOCKS              : h-reduce + tanh(h@W) (scheduled last)
// ---------------------------------------------------------------------------
__global__ void __launch_bounds__(256, 8) fused_kernel(
        const float* __restrict__ x,
        const float* __restrict__ nodes,
        const float* __restrict__ adj,
        const int* __restrict__ num_nodes,
        const float* __restrict__ W,
        float* __restrict__ nodes_out,
        float* __restrict__ adj_out,
        float* __restrict__ mx,
        float* __restrict__ nn_out) {
    const int blk = blockIdx.x;
    const int t   = threadIdx.x;

    if (blk >= NODES_BLOCKS + ADJ_BLOCKS) {
        // ---------------- mx path (last blocks) ----------------
        const int k = blk - (NODES_BLOCKS + ADJ_BLOCKS);
        const int b = k >> 2;            // batch
        const int q = k & 3;             // output quarter

        if (t == 0) {
            while (atomicAdd(&g_done, 0u) < NODES_BLOCKS) { __nanosleep(64); }
        }
        __syncthreads();
        __threadfence();

        __shared__ float h[FF];
        __shared__ float red[4][64];

        // reduce 32 partials -> h[256]
        {
            const float* base = g_hpart + (size_t)b * PARTIALS * FF + t;
            float acc = 0.f;
            #pragma unroll
            for (int p = 0; p < PARTIALS; p++) acc += base[p * FF];
            h[t] = acc;
        }
        __syncthreads();

        const int o  = (t & 63);
        const int fp = (t >> 6);
        const int f0 = fp * 64;
        const int oc = q * 64 + o;       // global output column
        float acc = 0.f;
        #pragma unroll 8
        for (int i = 0; i < 64; i++) {
            acc += h[f0 + i] * W[(size_t)(f0 + i) * FF + oc];
        }
        red[fp][o] = acc;
        __syncthreads();
        if (t < 64) {
            float s = red[0][t] + red[1][t] + red[2][t] + red[3][t];
            mx[(size_t)b * FF + q * 64 + t] = tanhf(s);
        }
        if (t == 0 && q == 0) {
            const int nn = num_nodes[b];
            nn_out[b] = (nn >= NN) ? (float)NN : (float)(nn + 1);
        }
        // self-reset: the last mx block past the spin restores the counters
        if (t == 0) {
            const unsigned r = atomicAdd(&g_mxdone, 1u);
            if (r == MX_BLOCKS - 1) {
                atomicExch(&g_done, 0u);
                atomicExch(&g_mxdone, 0u);
            }
        }
        return;
    }

    if (blk >= NODES_BLOCKS) {
        // ---------------- adj copy path: 4 rows, MLP=4, streaming ----------
        const int k  = blk - NODES_BLOCKS;
        const int rb = NN / ROWS_PER_ADJ_BLOCK;    // 256 blocks per batch
        const int b  = k / rb;
        const int r0 = (k % rb) * ROWS_PER_ADJ_BLOCK;
        const bool masked = num_nodes[b] >= NN;
        const size_t base = (size_t)b * NN * NN;

        if (!masked) {
            const float4* in4  = (const float4*)(adj + base);
            float4*       out4 = (float4*)(adj_out + base);
            const size_t i0 = (size_t)r0 * (NN / 4) + t;   // row = 256 float4
            // front-batched independent loads, evict-first both directions
            float4 v0 = __ldcs(in4 + i0);
            float4 v1 = __ldcs(in4 + i0 + 256);
            float4 v2 = __ldcs(in4 + i0 + 512);
            float4 v3 = __ldcs(in4 + i0 + 768);
            __stcs(out4 + i0,       v0);
            __stcs(out4 + i0 + 256, v1);
            __stcs(out4 + i0 + 512, v2);
            __stcs(out4 + i0 + 768, v3);
        } else {
            #pragma unroll
            for (int r = 0; r < ROWS_PER_ADJ_BLOCK; r++) {
                const int row = r0 + r;
                float4 v;
                if (row == NN - 1) {
                    v = make_float4(0.f, 0.f, 0.f, 0.f);
                } else {
                    const float* src = adj + base + (size_t)(row + 1) * NN;
                    const int j = t * 4;
                    v.x = src[j + 1];
                    v.y = src[j + 2];
                    v.z = src[j + 3];
                    v.w = (j + 3 == NN - 1) ? 0.f : src[j + 4];
                }
                __stcs((float4*)(adj_out + base + (size_t)row * NN) + t, v);
            }
        }
        return;
    }

    // ---------------- nodes copy + partial GEMV path ----------------
    const int s = blk & (S_SLICES - 1);
    const int b = blk / S_SLICES;
    const int nn = num_nodes[b];
    const bool masked = nn >= NN;
    const int nb = masked ? NN - 1 : nn;

    const int F4   = FF / 4;                     // 64
    const int f4   = t & (F4 - 1);
    const int msub = t >> 6;                     // 0..3
    const int rows_per_slice = NN / S_SLICES;    // 128
    const int row0 = s * rows_per_slice;

    const size_t nbase = (size_t)b * NN * FF;
    const float* adjrow = adj + (size_t)b * NN * NN + (size_t)nb * NN;
    const float4 xv = ((const float4*)(x + b * FF))[f4];

    float4 hacc = make_float4(0.f, 0.f, 0.f, 0.f);

    #pragma unroll 4
    for (int m = row0 + msub; m < row0 + rows_per_slice; m += 4) {
        float4 v;
        if (m == nb) {
            v = xv;                               // scatter-write of new memory x
        } else {
            const int srcm = masked ? m + 1 : m;  // FIFO shift when wrapped
            v = __ldcs(((const float4*)(nodes + nbase + (size_t)srcm * FF)) + f4);
        }
        __stcs(((float4*)(nodes_out + nbase + (size_t)m * FF)) + f4, v);

        if (!masked) {                            // masked => adj row nb is all-zero
            const float a = __ldg(adjrow + m);
            hacc.x += a * v.x; hacc.y += a * v.y;
            hacc.z += a * v.z; hacc.w += a * v.w;
        }
    }

    const int p = s * 4 + msub;
    ((float4*)(g_hpart + ((size_t)b * PARTIALS + p) * FF))[f4] = hacc;

    // publish this block's partials
    __syncthreads();
    __threadfence();
    if (t == 0) atomicAdd(&g_done, 1u);
}

// ---------------------------------------------------------------------------
// d_in: x[16384] f32, nodes[16777216] f32, adj[67108864] f32,
//       num_nodes[64] i32, W[65536] f32
// d_out (f32): mx[16384] | nodes[16777216] | adj[67108864] | num_nodes[64]
// ---------------------------------------------------------------------------
extern "C" void kernel_launch(void* const* d_in, const int* in_sizes, int n_in,
                              void* d_out, int out_size) {
    const float* x         = (const float*)d_in[0];
    const float* nodes     = (const float*)d_in[1];
    const float* adj       = (const float*)d_in[2];
    const int*   num_nodes = (const int*)  d_in[3];
    const float* W         = (const float*)d_in[4];

    float* out       = (float*)d_out;
    float* mx        = out;
    float* nodes_out = out + (size_t)BB * FF;
    float* adj_out   = nodes_out + (size_t)BB * NN * FF;
    float* nn_out    = adj_out + (size_t)BB * NN * NN;

    fused_kernel<<<NODES_BLOCKS + ADJ_BLOCKS + MX_BLOCKS, 256>>>(
        x, nodes, adj, num_nodes, W, nodes_out, adj_out, mx, nn_out);
}

// round 6
// speedup vs baseline: 1.2205x; 1.0194x over previous
#include <cuda_runtime.h>

#define BB 64
#define NN 1024
#define FF 256
#define S_SLICES 8
#define PARTIALS (S_SLICES * 4)      // 32 partial h vectors per batch
#define NODES_BLOCKS (S_SLICES * BB) // 512
#define ROWS_PER_ADJ_BLOCK 4
#define ADJ_BLOCKS   (BB * NN / ROWS_PER_ADJ_BLOCK)  // 16384
#define MX_BLOCKS    (BB * 4)        // 256 (batch x output-quarter)
// mx blocks are embedded mid-grid so they overlap the adj copy stream:
// dispatched ~wave 11 (>> nodes completion), well before the copy drains.
#define ADJ_FIRST    12500
#define MX_POS       (NODES_BLOCKS + ADJ_FIRST)
#define TOTAL_BLOCKS (NODES_BLOCKS + ADJ_BLOCKS + MX_BLOCKS)

// 2 MB scratch for GEMV partials + completion counters (allocation-free rule).
// Counters self-reset: zero at load; last mx block restores them each launch.
__device__ float g_hpart[BB * PARTIALS * FF];
__device__ unsigned int g_done;    // incremented by nodes blocks
__device__ unsigned int g_mxdone;  // incremented by mx blocks after their spin

__global__ void __launch_bounds__(256, 8) fused_kernel(
        const float* __restrict__ x,
        const float* __restrict__ nodes,
        const float* __restrict__ adj,
        const int* __restrict__ num_nodes,
        const float* __restrict__ W,
        float* __restrict__ nodes_out,
        float* __restrict__ adj_out,
        float* __restrict__ mx,
        float* __restrict__ nn_out) {
    const int blk = blockIdx.x;
    const int t   = threadIdx.x;

    if (blk >= MX_POS && blk < MX_POS + MX_BLOCKS) {
        // ---------------- mx path (mid-grid, overlaps adj copy) ------------
        const int k = blk - MX_POS;
        const int b = k >> 2;            // batch
        const int q = k & 3;             // output quarter

        if (t == 0) {
            while (atomicAdd(&g_done, 0u) < NODES_BLOCKS) { __nanosleep(64); }
        }
        __syncthreads();
        __threadfence();

        __shared__ float h[FF];
        __shared__ float red[4][64];

        // reduce 32 partials -> h[256]
        {
            const float* base = g_hpart + (size_t)b * PARTIALS * FF + t;
            float acc = 0.f;
            #pragma unroll
            for (int p = 0; p < PARTIALS; p++) acc += base[p * FF];
            h[t] = acc;
        }
        __syncthreads();

        const int o  = (t & 63);
        const int fp = (t >> 6);
        const int f0 = fp * 64;
        const int oc = q * 64 + o;       // global output column
        float acc = 0.f;
        #pragma unroll 8
        for (int i = 0; i < 64; i++) {
            acc += h[f0 + i] * W[(size_t)(f0 + i) * FF + oc];
        }
        red[fp][o] = acc;
        __syncthreads();
        if (t < 64) {
            float s = red[0][t] + red[1][t] + red[2][t] + red[3][t];
            mx[(size_t)b * FF + q * 64 + t] = tanhf(s);
        }
        if (t == 0 && q == 0) {
            const int nn = num_nodes[b];
            nn_out[b] = (nn >= NN) ? (float)NN : (float)(nn + 1);
        }
        // self-reset: the last mx block past the spin restores the counters
        if (t == 0) {
            const unsigned r = atomicAdd(&g_mxdone, 1u);
            if (r == MX_BLOCKS - 1) {
                atomicExch(&g_done, 0u);
                atomicExch(&g_mxdone, 0u);
            }
        }
        return;
    }

    if (blk >= NODES_BLOCKS) {
        // ---------------- adj copy path: 4 rows, MLP=4, streaming ----------
        const int k  = (blk < MX_POS) ? (blk - NODES_BLOCKS)
                                      : (blk - NODES_BLOCKS - MX_BLOCKS);
        const int rb = NN / ROWS_PER_ADJ_BLOCK;    // 256 blocks per batch
        const int b  = k / rb;
        const int r0 = (k % rb) * ROWS_PER_ADJ_BLOCK;
        const bool masked = num_nodes[b] >= NN;
        const size_t base = (size_t)b * NN * NN;

        if (!masked) {
            const float4* in4  = (const float4*)(adj + base);
            float4*       out4 = (float4*)(adj_out + base);
            const size_t i0 = (size_t)r0 * (NN / 4) + t;   // row = 256 float4
            float4 v0 = __ldcs(in4 + i0);
            float4 v1 = __ldcs(in4 + i0 + 256);
            float4 v2 = __ldcs(in4 + i0 + 512);
            float4 v3 = __ldcs(in4 + i0 + 768);
            __stcs(out4 + i0,       v0);
            __stcs(out4 + i0 + 256, v1);
            __stcs(out4 + i0 + 512, v2);
            __stcs(out4 + i0 + 768, v3);
        } else {
            #pragma unroll
            for (int r = 0; r < ROWS_PER_ADJ_BLOCK; r++) {
                const int row = r0 + r;
                float4 v;
                if (row == NN - 1) {
                    v = make_float4(0.f, 0.f, 0.f, 0.f);
                } else {
                    const float* src = adj + base + (size_t)(row + 1) * NN;
                    const int j = t * 4;
                    v.x = src[j + 1];
                    v.y = src[j + 2];
                    v.z = src[j + 3];
                    v.w = (j + 3 == NN - 1) ? 0.f : src[j + 4];
                }
                __stcs((float4*)(adj_out + base + (size_t)row * NN) + t, v);
            }
        }
        return;
    }

    // ---------------- nodes copy + partial GEMV path ----------------
    const int s = blk & (S_SLICES - 1);
    const int b = blk / S_SLICES;
    const int nn = num_nodes[b];
    const bool masked = nn >= NN;
    const int nb = masked ? NN - 1 : nn;

    const int F4   = FF / 4;                     // 64
    const int f4   = t & (F4 - 1);
    const int msub = t >> 6;                     // 0..3
    const int rows_per_slice = NN / S_SLICES;    // 128
    const int row0 = s * rows_per_slice;

    const size_t nbase = (size_t)b * NN * FF;
    const float* adjrow = adj + (size_t)b * NN * NN + (size_t)nb * NN;
    const float4 xv = ((const float4*)(x + b * FF))[f4];

    float4 hacc = make_float4(0.f, 0.f, 0.f, 0.f);

    #pragma unroll 8
    for (int m = row0 + msub; m < row0 + rows_per_slice; m += 4) {
        float4 v;
        if (m == nb) {
            v = xv;                               // scatter-write of new memory x
        } else {
            const int srcm = masked ? m + 1 : m;  // FIFO shift when wrapped
            v = __ldcs(((const float4*)(nodes + nbase + (size_t)srcm * FF)) + f4);
        }
        __stcs(((float4*)(nodes_out + nbase + (size_t)m * FF)) + f4, v);

        if (!masked) {                            // masked => adj row nb is all-zero
            const float a = __ldg(adjrow + m);
            hacc.x += a * v.x; hacc.y += a * v.y;
            hacc.z += a * v.z; hacc.w += a * v.w;
        }
    }

    const int p = s * 4 + msub;
    ((float4*)(g_hpart + ((size_t)b * PARTIALS + p) * FF))[f4] = hacc;

    // publish this block's partials
    __syncthreads();
    __threadfence();
    if (t == 0) atomicAdd(&g_done, 1u);
}

// ---------------------------------------------------------------------------
// d_in: x[16384] f32, nodes[16777216] f32, adj[67108864] f32,
//       num_nodes[64] i32, W[65536] f32
// d_out (f32): mx[16384] | nodes[16777216] | adj[67108864] | num_nodes[64]
// ---------------------------------------------------------------------------
extern "C" void kernel_launch(void* const* d_in, const int* in_sizes, int n_in,
                              void* d_out, int out_size) {
    const float* x         = (const float*)d_in[0];
    const float* nodes     = (const float*)d_in[1];
    const float* adj       = (const float*)d_in[2];
    const int*   num_nodes = (const int*)  d_in[3];
    const float* W         = (const float*)d_in[4];

    float* out       = (float*)d_out;
    float* mx        = out;
    float* nodes_out = out + (size_t)BB * FF;
    float* adj_out   = nodes_out + (size_t)BB * NN * FF;
    float* nn_out    = adj_out + (size_t)BB * NN * NN;

    fused_kernel<<<TOTAL_BLOCKS, 256>>>(
        x, nodes, adj, num_nodes, W, nodes_out, adj_out, mx, nn_out);
}

// round 7
// speedup vs baseline: 1.2722x; 1.0423x over previous
#include <cuda_runtime.h>

#define BB 64
#define NN 1024
#define FF 256
#define S_SLICES 8
#define PARTIALS (S_SLICES * 4)      // 32 partial h vectors per batch
#define NODES_BLOCKS (S_SLICES * BB) // 512
#define MX_BLOCKS    (BB * 4)        // 256 (batch x output-quarter)
#define GRID_BLOCKS  1184            // 148 SMs x 8 blocks: exactly one wave
#define ROWS_PER_CHUNK 2
#define ADJ_CHUNKS (BB * NN / ROWS_PER_CHUNK)       // 32768
#define CHUNKS_PER_BATCH (NN / ROWS_PER_CHUNK)      // 512

// 2 MB scratch for GEMV partials + counters (allocation-free rule).
// Counters self-reset deterministically: every block makes exactly one
// overflow fetch on g_work, so the fetch returning ADJ_CHUNKS+GRID_BLOCKS-1
// is the final atomic of the launch; that block zeroes g_work and g_done.
__device__ float g_hpart[BB * PARTIALS * FF];
__device__ unsigned int g_done;    // nodes-blocks completion counter
__device__ unsigned int g_work;    // adj chunk work-steal counter

__global__ void __launch_bounds__(256, 8) fused_kernel(
        const float* __restrict__ x,
        const float* __restrict__ nodes,
        const float* __restrict__ adj,
        const int* __restrict__ num_nodes,
        const float* __restrict__ W,
        float* __restrict__ nodes_out,
        float* __restrict__ adj_out,
        float* __restrict__ mx,
        float* __restrict__ nn_out) {
    const int blk = blockIdx.x;
    const int t   = threadIdx.x;

    __shared__ unsigned s_idx;
    __shared__ float h[FF];
    __shared__ float red[4][64];

    // ---------------- phase 1: nodes copy + partial GEMV (blocks 0..511) ---
    if (blk < NODES_BLOCKS) {
        const int s = blk & (S_SLICES - 1);
        const int b = blk / S_SLICES;
        const int nn = num_nodes[b];
        const bool masked = nn >= NN;
        const int nb = masked ? NN - 1 : nn;

        const int F4   = FF / 4;                     // 64
        const int f4   = t & (F4 - 1);
        const int msub = t >> 6;                     // 0..3
        const int rows_per_slice = NN / S_SLICES;    // 128
        const int row0 = s * rows_per_slice;

        const size_t nbase = (size_t)b * NN * FF;
        const float* adjrow = adj + (size_t)b * NN * NN + (size_t)nb * NN;
        const float4 xv = ((const float4*)(x + b * FF))[f4];

        float4 hacc = make_float4(0.f, 0.f, 0.f, 0.f);

        #pragma unroll 8
        for (int m = row0 + msub; m < row0 + rows_per_slice; m += 4) {
            float4 v;
            if (m == nb) {
                v = xv;                               // scatter-write of x
            } else {
                const int srcm = masked ? m + 1 : m;  // FIFO shift if wrapped
                v = __ldcs(((const float4*)(nodes + nbase + (size_t)srcm * FF)) + f4);
            }
            __stcs(((float4*)(nodes_out + nbase + (size_t)m * FF)) + f4, v);

            if (!masked) {                            // masked => row nb zero
                const float a = __ldg(adjrow + m);
                hacc.x += a * v.x; hacc.y += a * v.y;
                hacc.z += a * v.z; hacc.w += a * v.w;
            }
        }

        const int p = s * 4 + msub;
        ((float4*)(g_hpart + ((size_t)b * PARTIALS + p) * FF))[f4] = hacc;

        __syncthreads();
        __threadfence();
        if (t == 0) atomicAdd(&g_done, 1u);
    }

    // ---------------- phase 2: mx (blocks 0..255, all co-resident) --------
    if (blk < MX_BLOCKS) {
        const int b = blk >> 2;          // batch
        const int q = blk & 3;           // output quarter

        if (t == 0) {
            while (atomicAdd(&g_done, 0u) < NODES_BLOCKS) { __nanosleep(32); }
        }
        __syncthreads();
        __threadfence();

        // reduce 32 partials -> h[256]
        {
            const float* base = g_hpart + (size_t)b * PARTIALS * FF + t;
            float acc = 0.f;
            #pragma unroll
            for (int p = 0; p < PARTIALS; p++) acc += base[p * FF];
            h[t] = acc;
        }
        __syncthreads();

        const int o  = (t & 63);
        const int fp = (t >> 6);
        const int f0 = fp * 64;
        const int oc = q * 64 + o;       // global output column
        float acc = 0.f;
        #pragma unroll 8
        for (int i = 0; i < 64; i++) {
            acc += h[f0 + i] * W[(size_t)(f0 + i) * FF + oc];
        }
        red[fp][o] = acc;
        __syncthreads();
        if (t < 64) {
            float sres = red[0][t] + red[1][t] + red[2][t] + red[3][t];
            mx[(size_t)b * FF + q * 64 + t] = tanhf(sres);
        }
        if (t == 0 && q == 0) {
            const int nn = num_nodes[b];
            nn_out[b] = (nn >= NN) ? (float)NN : (float)(nn + 1);
        }
    }

    // ---------------- phase 3: adj copy via work stealing (all blocks) ----
    for (;;) {
        __syncthreads();     // prior iter's readers done with s_idx
        if (t == 0) s_idx = atomicAdd(&g_work, 1u);
        __syncthreads();
        const unsigned i = s_idx;

        if (i >= ADJ_CHUNKS) {
            // exactly one overflow fetch per block; the last one resets
            if (t == 0 && i == ADJ_CHUNKS + GRID_BLOCKS - 1) {
                atomicExch(&g_work, 0u);
                atomicExch(&g_done, 0u);
            }
            break;
        }

        const int b  = i >> 9;                       // / CHUNKS_PER_BATCH
        const int r0 = (i & (CHUNKS_PER_BATCH - 1)) * ROWS_PER_CHUNK;
        const bool masked = __ldg(num_nodes + b) >= NN;
        const size_t base = (size_t)b * NN * NN;

        if (!masked) {
            const float4* in4  = (const float4*)(adj + base);
            float4*       out4 = (float4*)(adj_out + base);
            const size_t i0 = (size_t)r0 * (NN / 4) + t;   // row = 256 float4
            float4 v0 = __ldcs(in4 + i0);
            float4 v1 = __ldcs(in4 + i0 + 256);
            __stcs(out4 + i0,       v0);
            __stcs(out4 + i0 + 256, v1);
        } else {
            #pragma unroll
            for (int r = 0; r < ROWS_PER_CHUNK; r++) {
                const int row = r0 + r;
                float4 v;
                if (row == NN - 1) {
                    v = make_float4(0.f, 0.f, 0.f, 0.f);
                } else {
                    const float* src = adj + base + (size_t)(row + 1) * NN;
                    const int j = t * 4;
                    v.x = src[j + 1];
                    v.y = src[j + 2];
                    v.z = src[j + 3];
                    v.w = (j + 3 == NN - 1) ? 0.f : src[j + 4];
                }
                __stcs((float4*)(adj_out + base + (size_t)row * NN) + t, v);
            }
        }
    }
}

// ---------------------------------------------------------------------------
// d_in: x[16384] f32, nodes[16777216] f32, adj[67108864] f32,
//       num_nodes[64] i32, W[65536] f32
// d_out (f32): mx[16384] | nodes[16777216] | adj[67108864] | num_nodes[64]
// ---------------------------------------------------------------------------
extern "C" void kernel_launch(void* const* d_in, const int* in_sizes, int n_in,
                              void* d_out, int out_size) {
    const float* x         = (const float*)d_in[0];
    const float* nodes     = (const float*)d_in[1];
    const float* adj       = (const float*)d_in[2];
    const int*   num_nodes = (const int*)  d_in[3];
    const float* W         = (const float*)d_in[4];

    float* out       = (float*)d_out;
    float* mx        = out;
    float* nodes_out = out + (size_t)BB * FF;
    float* adj_out   = nodes_out + (size_t)BB * NN * FF;
    float* nn_out    = adj_out + (size_t)BB * NN * NN;

    fused_kernel<<<GRID_BLOCKS, 256>>>(
        x, nodes, adj, num_nodes, W, nodes_out, adj_out, mx, nn_out);
}